// round 3
// baseline (speedup 1.0000x reference)
#include <cuda_runtime.h>
#include <math.h>

#define B_   32
#define DF_  2048
#define NC_  1023
#define NCP_ 1024

typedef unsigned long long ull;

// ---- packed f32x2 helpers (Blackwell) ----
__device__ __forceinline__ ull PK(float lo, float hi) {
    ull r; asm("mov.b64 %0,{%1,%2};" : "=l"(r) : "f"(lo), "f"(hi)); return r;
}
__device__ __forceinline__ void UPK(ull v, float& a, float& b) {
    asm("mov.b64 {%0,%1},%2;" : "=f"(a), "=f"(b) : "l"(v));
}
__device__ __forceinline__ ull FMA2(ull a, ull b, ull c) {
    ull d; asm("fma.rn.f32x2 %0,%1,%2,%3;" : "=l"(d) : "l"(a), "l"(b), "l"(c)); return d;
}
__device__ __forceinline__ ull ADD2(ull a, ull b) {
    ull d; asm("add.rn.f32x2 %0,%1,%2;" : "=l"(d) : "l"(a), "l"(b)); return d;
}
__device__ __forceinline__ ull MUL2(ull a, ull b) {
    ull d; asm("mul.rn.f32x2 %0,%1,%2;" : "=l"(d) : "l"(a), "l"(b)); return d;
}

// ---- cp.async helpers ----
__device__ __forceinline__ void cpasync16(void* dst_smem, const void* src) {
    unsigned d = (unsigned)__cvta_generic_to_shared(dst_smem);
    asm volatile("cp.async.cg.shared.global [%0], [%1], 16;" :: "r"(d), "l"(src));
}
__device__ __forceinline__ void cp_commit() {
    asm volatile("cp.async.commit_group;");
}
template <int N>
__device__ __forceinline__ void cp_wait() {
    asm volatile("cp.async.wait_group %0;" :: "n"(N));
}

// ---------------- scratch ----------------
__device__ float g_LN[B_ * DF_];
__device__ float g_S[B_ * NCP_];
__device__ float g_V[B_ * NCP_];
__device__ float g_smax[B_];
__device__ float g_smin[B_];
__device__ float g_OUT1[B_ * DF_];
__device__ float g_LN2[B_ * DF_];
__device__ float g_H[B_ * DF_];

// ============================================================================
// K1: per-batch preprocess (unchanged)
// ============================================================================
__global__ void prep_kernel(const float* __restrict__ feat,
                            const int*   __restrict__ idx,
                            const float* __restrict__ ln_w,
                            const float* __restrict__ ln_b,
                            const float* __restrict__ q_w,
                            const float* __restrict__ k_w,
                            const float* __restrict__ v_w,
                            const float* __restrict__ conv_w) {
    __shared__ float sf[DF_];
    __shared__ float sh[DF_];
    __shared__ float kred[4][128];
    __shared__ float vred[4][128];
    __shared__ float red1[8], red2[8];

    const int b = blockIdx.x;
    const int tid = threadIdx.x;

    float s1 = 0.f, s2 = 0.f;
    for (int i = tid; i < DF_; i += 256) {
        float v = feat[b * DF_ + i];
        sf[i] = v;
        s1 += v;
        s2 = fmaf(v, v, s2);
    }

    if (tid < 128) {
        float qw = q_w[tid];
        float cw = conv_w[tid];
        #pragma unroll
        for (int j = 0; j < 4; j++) {
            kred[j][tid] = qw * k_w[tid * 4 + j];
            vred[j][tid] = cw * v_w[tid * 4 + j];
        }
    }

    #pragma unroll
    for (int o = 16; o; o >>= 1) {
        s1 += __shfl_xor_sync(~0u, s1, o);
        s2 += __shfl_xor_sync(~0u, s2, o);
    }
    if ((tid & 31) == 0) { red1[tid >> 5] = s1; red2[tid >> 5] = s2; }
    __syncthreads();

    if (tid < 64) {
        #pragma unroll
        for (int j = 0; j < 4; j++) {
            kred[j][tid] += kred[j][tid + 64];
            vred[j][tid] += vred[j][tid + 64];
        }
    }
    __syncthreads();
    if (tid < 32) {
        #pragma unroll
        for (int j = 0; j < 4; j++) {
            float kv = kred[j][tid] + kred[j][tid + 32];
            float vv = vred[j][tid] + vred[j][tid + 32];
            #pragma unroll
            for (int o = 16; o; o >>= 1) {
                kv += __shfl_xor_sync(~0u, kv, o);
                vv += __shfl_xor_sync(~0u, vv, o);
            }
            if (tid == 0) { kred[j][0] = kv; vred[j][0] = vv; }
        }
    }
    __syncthreads();

    float S1 = 0.f, S2 = 0.f;
    #pragma unroll
    for (int i = 0; i < 8; i++) { S1 += red1[i]; S2 += red2[i]; }
    const float mean = S1 * (1.f / DF_);
    const float var  = S2 * (1.f / DF_) - mean * mean;
    const float rstd = rsqrtf(var + 1e-5f);

    for (int i = tid; i < DF_; i += 256) {
        g_LN[b * DF_ + i] = (sf[i] - mean) * rstd * ln_w[i] + ln_b[i];
        sh[i] = sf[idx[i]];
    }
    __syncthreads();

    const float kw0 = kred[0][0], kw1 = kred[1][0], kw2 = kred[2][0], kw3 = kred[3][0];
    const float vw0 = vred[0][0], vw1 = vred[1][0], vw2 = vred[2][0], vw3 = vred[3][0];

    float lmax = -3.4e38f, lmin = 3.4e38f;
    for (int c = tid; c < NCP_; c += 256) {
        float s = 0.f, v = 0.f;
        if (c < NC_) {
            float x0 = sh[2 * c], x1 = sh[2 * c + 1], x2 = sh[2 * c + 2], x3 = sh[2 * c + 3];
            s = fmaf(x3, kw3, fmaf(x2, kw2, fmaf(x1, kw1, x0 * kw0)));
            v = fmaf(x3, vw3, fmaf(x2, vw2, fmaf(x1, vw1, x0 * vw0)));
            lmax = fmaxf(lmax, s);
            lmin = fminf(lmin, s);
        }
        g_S[b * NCP_ + c] = s;
        g_V[b * NCP_ + c] = v;
    }
    #pragma unroll
    for (int o = 16; o; o >>= 1) {
        lmax = fmaxf(lmax, __shfl_xor_sync(~0u, lmax, o));
        lmin = fminf(lmin, __shfl_xor_sync(~0u, lmin, o));
    }
    __syncthreads();
    if ((tid & 31) == 0) { red1[tid >> 5] = lmax; red2[tid >> 5] = lmin; }
    __syncthreads();
    if (tid == 0) {
        float mx = red1[0], mn = red2[0];
        #pragma unroll
        for (int i = 1; i < 8; i++) { mx = fmaxf(mx, red1[i]); mn = fminf(mn, red2[i]); }
        g_smax[b] = mx;
        g_smin[b] = mn;
    }
}

// ============================================================================
// K2: softmax + attn output. Lane owns a CONTIGUOUS 32-element block
// (smem transposed for conflict-free reads); aligned STG.128 store path.
// ============================================================================
__global__ __launch_bounds__(256) void attn_kernel(const float* __restrict__ feat,
                                                   float* __restrict__ dout) {
    __shared__ __align__(16) float2 ss2[512];
    __shared__ __align__(16) float2 sv2[512];

    const int b = blockIdx.x;
    const int chunk = blockIdx.y;
    const int tid = threadIdx.x;
    const int lane = tid & 31;
    const int w = tid >> 5;

    // transposed fill: pair p (elements 2p,2p+1) -> slot (p%16)*32 + p/16
    const float2* gs = (const float2*)(g_S + b * NCP_);
    const float2* gv = (const float2*)(g_V + b * NCP_);
    for (int i = tid; i < 512; i += 256) {
        int slot = (i & 15) * 32 + (i >> 4);
        ss2[slot] = gs[i];
        sv2[slot] = gv[i];
    }
    __syncthreads();

    const float smax = g_smax[b];
    const float smin = g_smin[b];
    const float LOG2E = 1.4426950408889634f;
    const ull C5 = PK(0.00133335581464284f, 0.00133335581464284f);
    const ull C4 = PK(0.00961812910762848f, 0.00961812910762848f);
    const ull C3 = PK(0.05550410866482158f, 0.05550410866482158f);
    const ull C2 = PK(0.24022650695910071f, 0.24022650695910071f);
    const ull C1 = PK(0.69314718055994531f, 0.69314718055994531f);
    const ull ONE = PK(1.0f, 1.0f);

    const bool last = (lane == 31);

    for (int r = 0; r < 16; ++r) {
        const int q = chunk * 128 + r * 8 + w;
        const int row = b * DF_ + q;
        const float alpha = g_LN[row];
        const float al = alpha * LOG2E;
        const float m = (alpha >= 0.f) ? smax : smin;
        const float nb = -al * m;
        const ull al2 = PK(al, al);
        const ull nb2 = PK(nb, nb);

        ull p2[16];
        ull sum2 = PK(0.f, 0.f), dot2 = PK(0.f, 0.f);
        #pragma unroll
        for (int j = 0; j < 16; ++j) {
            float2 s2 = ss2[j * 32 + lane];
            float2 v2 = sv2[j * 32 + lane];
            ull x = FMA2(al2, PK(s2.x, s2.y), nb2);
            ull pf = FMA2(x, C5, C4);
            pf = FMA2(x, pf, C3);
            pf = FMA2(x, pf, C2);
            pf = FMA2(x, pf, C1);
            pf = FMA2(x, pf, ONE);
            if (j == 15) {     // element c = lane*32+31; mask c==1023
                float a_, b_; UPK(pf, a_, b_);
                if (last) b_ = 0.f;
                pf = PK(a_, b_);
            }
            p2[j] = pf;
            sum2 = ADD2(sum2, pf);
            dot2 = FMA2(pf, PK(v2.x, v2.y), dot2);
        }

        float slo, shi, dlo, dhi;
        UPK(sum2, slo, shi);
        UPK(dot2, dlo, dhi);
        float sum = slo + shi;
        float dot = dlo + dhi;
        #pragma unroll
        for (int o = 16; o; o >>= 1) {
            sum += __shfl_xor_sync(~0u, sum, o);
            dot += __shfl_xor_sync(~0u, dot, o);
        }
        const float inv = 1.0f / sum;
        const ull inv2 = PK(inv, inv);

        float E[32];
        #pragma unroll
        for (int j = 0; j < 16; ++j) {
            ull o2 = MUL2(p2[j], inv2);
            UPK(o2, E[2 * j], E[2 * j + 1]);
        }

        float* bp = dout + 65536 + (size_t)row * NC_ + lane * 32;
        const int lead = row & 3;   // (start + lead) is 16B aligned

        #define F4(a) make_float4(E[(a)], E[(a)+1], E[(a)+2], E[(a)+3])
        switch (lead) {
        case 0:
            #pragma unroll
            for (int t = 0; t < 7; ++t) __stcs((float4*)(bp + 4 * t), F4(4 * t));
            if (!last) __stcs((float4*)(bp + 28), F4(28));
            else { __stcs(bp + 28, E[28]); __stcs(bp + 29, E[29]); __stcs(bp + 30, E[30]); }
            break;
        case 1:
            __stcs(bp, E[0]);
            #pragma unroll
            for (int t = 0; t < 7; ++t) __stcs((float4*)(bp + 1 + 4 * t), F4(1 + 4 * t));
            __stcs(bp + 29, E[29]); __stcs(bp + 30, E[30]);
            if (!last) __stcs(bp + 31, E[31]);
            break;
        case 2:
            __stcs(bp, E[0]); __stcs(bp + 1, E[1]);
            #pragma unroll
            for (int t = 0; t < 7; ++t) __stcs((float4*)(bp + 2 + 4 * t), F4(2 + 4 * t));
            __stcs(bp + 30, E[30]);
            if (!last) __stcs(bp + 31, E[31]);
            break;
        default:
            __stcs(bp, E[0]); __stcs(bp + 1, E[1]); __stcs(bp + 2, E[2]);
            #pragma unroll
            for (int t = 0; t < 7; ++t) __stcs((float4*)(bp + 3 + 4 * t), F4(3 + 4 * t));
            if (!last) __stcs(bp + 31, E[31]);
            break;
        }
        #undef F4

        if (lane == 0) {
            g_OUT1[row] = fmaf(dot, inv, feat[row]);
        }
    }
}

// ============================================================================
// K3: FFN prep (unchanged)
// ============================================================================
__global__ void ffn_prep_kernel(const float* __restrict__ bn_w,
                                const float* __restrict__ bn_b,
                                const float* __restrict__ w1_b,
                                const float* __restrict__ w2_b,
                                float* __restrict__ dout) {
    __shared__ float row[DF_];
    __shared__ float red1[8], red2[8];
    const int m = blockIdx.x;
    const int tid = threadIdx.x;

    float s1 = 0.f, s2 = 0.f;
    for (int i = tid; i < DF_; i += 256) {
        float v = g_OUT1[m * DF_ + i];
        row[i] = v;
        s1 += v;
        s2 = fmaf(v, v, s2);
    }
    #pragma unroll
    for (int o = 16; o; o >>= 1) {
        s1 += __shfl_xor_sync(~0u, s1, o);
        s2 += __shfl_xor_sync(~0u, s2, o);
    }
    if ((tid & 31) == 0) { red1[tid >> 5] = s1; red2[tid >> 5] = s2; }
    __syncthreads();
    float S1 = 0.f, S2 = 0.f;
    #pragma unroll
    for (int i = 0; i < 8; i++) { S1 += red1[i]; S2 += red2[i]; }
    const float mean = S1 * (1.f / DF_);
    const float var  = S2 * (1.f / DF_) - mean * mean;
    const float rstd = rsqrtf(var + 1e-6f);

    for (int i = tid; i < DF_; i += 256) {
        g_LN2[m * DF_ + i] = (row[i] - mean) * rstd * bn_w[i] + bn_b[i];
        g_H[m * DF_ + i]   = w1_b[i];
        dout[m * DF_ + i]  = w2_b[i] + row[i];
    }
}

// ============================================================================
// K4/K5: GEMM v3. cp.async 3-buffer pipeline for W; A k-slice staged once,
// transposed [k][m] (lane=m conflict-free). Tile 64n x 128k, grid (32,16).
// C[m,n] += sum_k A[m,k]*W[n,k]. Epilogue RED.ADD.
// ============================================================================
__global__ __launch_bounds__(256) void gemm_kernel(int mode,
                                                   const float* __restrict__ W,
                                                   float* __restrict__ outp) {
    __shared__ float As[128][33];                       // 16.9 KB, [k][m]
    __shared__ __align__(16) float Ws[3][64][36];       // 27.6 KB, 3 stages x (64n x 32k)

    const float* A = (mode == 0) ? g_LN2 : g_H;
    float* C       = (mode == 0) ? g_H   : outp;

    const int n0 = blockIdx.x * 64;
    const int k0 = blockIdx.y * 128;
    const int tid = threadIdx.x;
    const int lane = tid & 31;
    const int wid = tid >> 5;

    // ---- issue W stage s (s in 0..3, 32 k each) via cp.async ----
    auto issueW = [&](int s) {
        const int buf = s % 3;
        #pragma unroll
        for (int j = 0; j < 2; ++j) {
            int idx = tid + 256 * j;          // 0..511 (512 x 16B = 8KB)
            int n = idx >> 3, qd = idx & 7;
            cpasync16(&Ws[buf][n][qd * 4],
                      &W[(size_t)(n0 + n) * DF_ + k0 + s * 32 + qd * 4]);
        }
        cp_commit();
    };

    issueW(0);
    issueW(1);

    // ---- A slice: 32m x 128k, transposed into As[k][m] ----
    {
        const int m = tid >> 3;
        const int kq = (tid & 7) * 4;
        #pragma unroll
        for (int it = 0; it < 4; ++it) {
            const int k = kq + 32 * it;
            float4 v = *(const float4*)&A[m * DF_ + k0 + k];
            if (mode) {
                v.x = fmaxf(v.x, 0.f); v.y = fmaxf(v.y, 0.f);
                v.z = fmaxf(v.z, 0.f); v.w = fmaxf(v.w, 0.f);
            }
            As[k + 0][m] = v.x;
            As[k + 1][m] = v.y;
            As[k + 2][m] = v.z;
            As[k + 3][m] = v.w;
        }
    }

    float acc[8];
    #pragma unroll
    for (int i = 0; i < 8; ++i) acc[i] = 0.f;

    #pragma unroll
    for (int s = 0; s < 4; ++s) {
        if (s < 3) cp_wait<1>(); else cp_wait<0>();
        __syncthreads();
        if (s + 2 < 4) issueW(s + 2);

        const int buf = s % 3;
        #pragma unroll
        for (int k4 = 0; k4 < 8; ++k4) {
            const int kb = s * 32 + k4 * 4;
            float a0 = As[kb + 0][lane];
            float a1 = As[kb + 1][lane];
            float a2 = As[kb + 2][lane];
            float a3 = As[kb + 3][lane];
            #pragma unroll
            for (int nn = 0; nn < 8; ++nn) {
                float4 wv = *(const float4*)&Ws[buf][wid * 8 + nn][k4 * 4];
                acc[nn] = fmaf(a0, wv.x,
                          fmaf(a1, wv.y,
                          fmaf(a2, wv.z,
                          fmaf(a3, wv.w, acc[nn]))));
            }
        }
    }

    #pragma unroll
    for (int nn = 0; nn < 8; ++nn)
        atomicAdd(&C[lane * DF_ + n0 + wid * 8 + nn], acc[nn]);
}

// ============================================================================
extern "C" void kernel_launch(void* const* d_in, const int* in_sizes, int n_in,
                              void* d_out, int out_size) {
    const float* feat   = (const float*)d_in[0];
    const int*   idx    = (const int*)  d_in[1];
    const float* ln_w   = (const float*)d_in[2];
    const float* ln_b   = (const float*)d_in[3];
    const float* q_w    = (const float*)d_in[4];
    const float* k_w    = (const float*)d_in[5];
    const float* v_w    = (const float*)d_in[6];
    const float* conv_w = (const float*)d_in[7];
    const float* bn_w   = (const float*)d_in[8];
    const float* bn_b   = (const float*)d_in[9];
    const float* w1_w   = (const float*)d_in[10];
    const float* w1_b   = (const float*)d_in[11];
    const float* w2_w   = (const float*)d_in[12];
    const float* w2_b   = (const float*)d_in[13];
    float* out = (float*)d_out;

    prep_kernel<<<B_, 256>>>(feat, idx, ln_w, ln_b, q_w, k_w, v_w, conv_w);
    attn_kernel<<<dim3(B_, 16), 256>>>(feat, out);
    ffn_prep_kernel<<<B_, 256>>>(bn_w, bn_b, w1_b, w2_b, out);
    gemm_kernel<<<dim3(32, 16), 256>>>(0, w1_w, out);
    gemm_kernel<<<dim3(32, 16), 256>>>(1, w2_w, out);
}

// round 4
// speedup vs baseline: 2.1892x; 2.1892x over previous
#include <cuda_runtime.h>
#include <math.h>

#define B_   32
#define DF_  2048
#define NC_  1023
#define NCP_ 1024

typedef unsigned long long ull;

// ---- packed f32x2 helpers (Blackwell) ----
__device__ __forceinline__ ull PK(float lo, float hi) {
    ull r; asm("mov.b64 %0,{%1,%2};" : "=l"(r) : "f"(lo), "f"(hi)); return r;
}
__device__ __forceinline__ void UPK(ull v, float& a, float& b) {
    asm("mov.b64 {%0,%1},%2;" : "=f"(a), "=f"(b) : "l"(v));
}
__device__ __forceinline__ ull FMA2(ull a, ull b, ull c) {
    ull d; asm("fma.rn.f32x2 %0,%1,%2,%3;" : "=l"(d) : "l"(a), "l"(b), "l"(c)); return d;
}
__device__ __forceinline__ ull ADD2(ull a, ull b) {
    ull d; asm("add.rn.f32x2 %0,%1,%2;" : "=l"(d) : "l"(a), "l"(b)); return d;
}
__device__ __forceinline__ ull MUL2(ull a, ull b) {
    ull d; asm("mul.rn.f32x2 %0,%1,%2;" : "=l"(d) : "l"(a), "l"(b)); return d;
}

// ---- cp.async helpers ----
__device__ __forceinline__ void cpasync16(void* dst_smem, const void* src) {
    unsigned d = (unsigned)__cvta_generic_to_shared(dst_smem);
    asm volatile("cp.async.cg.shared.global [%0], [%1], 16;" :: "r"(d), "l"(src));
}
__device__ __forceinline__ void cp_commit() {
    asm volatile("cp.async.commit_group;");
}
template <int N>
__device__ __forceinline__ void cp_wait() {
    asm volatile("cp.async.wait_group %0;" :: "n"(N));
}

// ---------------- scratch ----------------
__device__ float g_LN[B_ * DF_];
__device__ float g_S[B_ * NCP_];
__device__ float g_V[B_ * NCP_];
__device__ float g_smax[B_];
__device__ float g_smin[B_];
__device__ float g_OUT1[B_ * DF_];
__device__ float g_LN2[B_ * DF_];
__device__ float g_H[B_ * DF_];

// ============================================================================
// K1: per-batch preprocess (unchanged)
// ============================================================================
__global__ void prep_kernel(const float* __restrict__ feat,
                            const int*   __restrict__ idx,
                            const float* __restrict__ ln_w,
                            const float* __restrict__ ln_b,
                            const float* __restrict__ q_w,
                            const float* __restrict__ k_w,
                            const float* __restrict__ v_w,
                            const float* __restrict__ conv_w) {
    __shared__ float sf[DF_];
    __shared__ float sh[DF_];
    __shared__ float kred[4][128];
    __shared__ float vred[4][128];
    __shared__ float red1[8], red2[8];

    const int b = blockIdx.x;
    const int tid = threadIdx.x;

    float s1 = 0.f, s2 = 0.f;
    for (int i = tid; i < DF_; i += 256) {
        float v = feat[b * DF_ + i];
        sf[i] = v;
        s1 += v;
        s2 = fmaf(v, v, s2);
    }

    if (tid < 128) {
        float qw = q_w[tid];
        float cw = conv_w[tid];
        #pragma unroll
        for (int j = 0; j < 4; j++) {
            kred[j][tid] = qw * k_w[tid * 4 + j];
            vred[j][tid] = cw * v_w[tid * 4 + j];
        }
    }

    #pragma unroll
    for (int o = 16; o; o >>= 1) {
        s1 += __shfl_xor_sync(~0u, s1, o);
        s2 += __shfl_xor_sync(~0u, s2, o);
    }
    if ((tid & 31) == 0) { red1[tid >> 5] = s1; red2[tid >> 5] = s2; }
    __syncthreads();

    if (tid < 64) {
        #pragma unroll
        for (int j = 0; j < 4; j++) {
            kred[j][tid] += kred[j][tid + 64];
            vred[j][tid] += vred[j][tid + 64];
        }
    }
    __syncthreads();
    if (tid < 32) {
        #pragma unroll
        for (int j = 0; j < 4; j++) {
            float kv = kred[j][tid] + kred[j][tid + 32];
            float vv = vred[j][tid] + vred[j][tid + 32];
            #pragma unroll
            for (int o = 16; o; o >>= 1) {
                kv += __shfl_xor_sync(~0u, kv, o);
                vv += __shfl_xor_sync(~0u, vv, o);
            }
            if (tid == 0) { kred[j][0] = kv; vred[j][0] = vv; }
        }
    }
    __syncthreads();

    float S1 = 0.f, S2 = 0.f;
    #pragma unroll
    for (int i = 0; i < 8; i++) { S1 += red1[i]; S2 += red2[i]; }
    const float mean = S1 * (1.f / DF_);
    const float var  = S2 * (1.f / DF_) - mean * mean;
    const float rstd = rsqrtf(var + 1e-5f);

    for (int i = tid; i < DF_; i += 256) {
        g_LN[b * DF_ + i] = (sf[i] - mean) * rstd * ln_w[i] + ln_b[i];
        sh[i] = sf[idx[i]];
    }
    __syncthreads();

    const float kw0 = kred[0][0], kw1 = kred[1][0], kw2 = kred[2][0], kw3 = kred[3][0];
    const float vw0 = vred[0][0], vw1 = vred[1][0], vw2 = vred[2][0], vw3 = vred[3][0];

    float lmax = -3.4e38f, lmin = 3.4e38f;
    for (int c = tid; c < NCP_; c += 256) {
        float s = 0.f, v = 0.f;
        if (c < NC_) {
            float x0 = sh[2 * c], x1 = sh[2 * c + 1], x2 = sh[2 * c + 2], x3 = sh[2 * c + 3];
            s = fmaf(x3, kw3, fmaf(x2, kw2, fmaf(x1, kw1, x0 * kw0)));
            v = fmaf(x3, vw3, fmaf(x2, vw2, fmaf(x1, vw1, x0 * vw0)));
            lmax = fmaxf(lmax, s);
            lmin = fminf(lmin, s);
        }
        g_S[b * NCP_ + c] = s;
        g_V[b * NCP_ + c] = v;
    }
    #pragma unroll
    for (int o = 16; o; o >>= 1) {
        lmax = fmaxf(lmax, __shfl_xor_sync(~0u, lmax, o));
        lmin = fminf(lmin, __shfl_xor_sync(~0u, lmin, o));
    }
    __syncthreads();
    if ((tid & 31) == 0) { red1[tid >> 5] = lmax; red2[tid >> 5] = lmin; }
    __syncthreads();
    if (tid == 0) {
        float mx = red1[0], mn = red2[0];
        #pragma unroll
        for (int i = 1; i < 8; i++) { mx = fmaxf(mx, red1[i]); mn = fminf(mn, red2[i]); }
        g_smax[b] = mx;
        g_smin[b] = mn;
    }
}

// ============================================================================
// K2: softmax + attn output. Round-2 compute layout (coalesced pairs) +
// per-warp smem staging so ALL global stores are aligned coalesced STG.128.
// ============================================================================
#define SBUF_PITCH 1056
__global__ __launch_bounds__(256) void attn_kernel(const float* __restrict__ feat,
                                                   float* __restrict__ dout) {
    __shared__ __align__(8)  float2 ss2[512];
    __shared__ __align__(8)  float2 sv2[512];
    __shared__ __align__(16) float sbuf[8 * SBUF_PITCH];

    const int b = blockIdx.x;
    const int chunk = blockIdx.y;
    const int tid = threadIdx.x;
    const int lane = tid & 31;
    const int w = tid >> 5;

    const float2* gs = (const float2*)(g_S + b * NCP_);
    const float2* gv = (const float2*)(g_V + b * NCP_);
    for (int i = tid; i < 512; i += 256) {
        ss2[i] = gs[i];
        sv2[i] = gv[i];
    }
    __syncthreads();

    const float smax = g_smax[b];
    const float smin = g_smin[b];
    const float LOG2E = 1.4426950408889634f;
    const ull C5 = PK(0.00133335581464284f, 0.00133335581464284f);
    const ull C4 = PK(0.00961812910762848f, 0.00961812910762848f);
    const ull C3 = PK(0.05550410866482158f, 0.05550410866482158f);
    const ull C2 = PK(0.24022650695910071f, 0.24022650695910071f);
    const ull C1 = PK(0.69314718055994531f, 0.69314718055994531f);
    const ull ONE = PK(1.0f, 1.0f);

    const bool lastlane = (lane == 31);
    float* const sb = sbuf + w * SBUF_PITCH;

    for (int r = 0; r < 16; ++r) {
        const int q = chunk * 128 + r * 8 + w;
        const int row = b * DF_ + q;
        const float alpha = g_LN[row];
        const float al = alpha * LOG2E;
        const float m = (alpha >= 0.f) ? smax : smin;
        const float nb = -al * m;
        const ull al2 = PK(al, al);
        const ull nb2 = PK(nb, nb);

        ull p2[16];
        ull sum2 = PK(0.f, 0.f), dot2 = PK(0.f, 0.f);
        #pragma unroll
        for (int i = 0; i < 16; ++i) {
            const int c2 = lane + 32 * i;
            float2 s2 = ss2[c2];
            float2 v2 = sv2[c2];
            ull x = FMA2(al2, PK(s2.x, s2.y), nb2);
            ull pf = FMA2(x, C5, C4);
            pf = FMA2(x, pf, C3);
            pf = FMA2(x, pf, C2);
            pf = FMA2(x, pf, C1);
            pf = FMA2(x, pf, ONE);
            if (i == 15) {     // mask element c=1023
                float a_, b_; UPK(pf, a_, b_);
                if (lastlane) b_ = 0.f;
                pf = PK(a_, b_);
            }
            p2[i] = pf;
            sum2 = ADD2(sum2, pf);
            dot2 = FMA2(pf, PK(v2.x, v2.y), dot2);
        }

        float slo, shi, dlo, dhi;
        UPK(sum2, slo, shi);
        UPK(dot2, dlo, dhi);
        float sum = slo + shi;
        float dot = dlo + dhi;
        #pragma unroll
        for (int o = 16; o; o >>= 1) {
            sum += __shfl_xor_sync(~0u, sum, o);
            dot += __shfl_xor_sync(~0u, dot, o);
        }
        const float inv = 1.0f / sum;
        const ull inv2 = PK(inv, inv);

        float* const base = dout + 65536 + (size_t)row * NC_;
        const int shift = (int)((size_t)base & 15) >> 2;   // = base&3 in floats
        const int lead = (4 - shift) & 3;

        // stage normalized row into sbuf at offset `shift`
        if ((shift & 1) == 0) {
            #pragma unroll
            for (int i = 0; i < 16; ++i) {
                float o0, o1; UPK(MUL2(p2[i], inv2), o0, o1);
                *(float2*)(sb + 2 * (lane + 32 * i) + shift) = make_float2(o0, o1);
            }
        } else {
            #pragma unroll
            for (int i = 0; i < 16; ++i) {
                float o0, o1; UPK(MUL2(p2[i], inv2), o0, o1);
                const int c = 2 * (lane + 32 * i) + shift;
                sb[c] = o0;
                sb[c + 1] = o1;
            }
        }
        __syncwarp();

        // coalesced, fully aligned copy-out
        if (lane < lead) __stcs(base + lane, sb[lane + shift]);
        const float4* s4 = (const float4*)(sb + lead + shift);   // 16B aligned
        float4* g4 = (float4*)(base + lead);
        #pragma unroll
        for (int j = 0; j < 8; ++j) {
            const int t = lane + 32 * j;
            if (t < 255) __stcs(g4 + t, s4[t]);
        }
        const int done = lead + 1020;
        const int tail = NC_ - done;      // 3 - lead
        if (lane < tail) __stcs(base + done + lane, sb[done + lane + shift]);

        if (lane == 0) {
            g_OUT1[row] = fmaf(dot, inv, feat[row]);
        }
        __syncwarp();
    }
}

// ============================================================================
// K3: FFN prep (unchanged)
// ============================================================================
__global__ void ffn_prep_kernel(const float* __restrict__ bn_w,
                                const float* __restrict__ bn_b,
                                const float* __restrict__ w1_b,
                                const float* __restrict__ w2_b,
                                float* __restrict__ dout) {
    __shared__ float row[DF_];
    __shared__ float red1[8], red2[8];
    const int m = blockIdx.x;
    const int tid = threadIdx.x;

    float s1 = 0.f, s2 = 0.f;
    for (int i = tid; i < DF_; i += 256) {
        float v = g_OUT1[m * DF_ + i];
        row[i] = v;
        s1 += v;
        s2 = fmaf(v, v, s2);
    }
    #pragma unroll
    for (int o = 16; o; o >>= 1) {
        s1 += __shfl_xor_sync(~0u, s1, o);
        s2 += __shfl_xor_sync(~0u, s2, o);
    }
    if ((tid & 31) == 0) { red1[tid >> 5] = s1; red2[tid >> 5] = s2; }
    __syncthreads();
    float S1 = 0.f, S2 = 0.f;
    #pragma unroll
    for (int i = 0; i < 8; i++) { S1 += red1[i]; S2 += red2[i]; }
    const float mean = S1 * (1.f / DF_);
    const float var  = S2 * (1.f / DF_) - mean * mean;
    const float rstd = rsqrtf(var + 1e-6f);

    for (int i = tid; i < DF_; i += 256) {
        g_LN2[m * DF_ + i] = (row[i] - mean) * rstd * bn_w[i] + bn_b[i];
        g_H[m * DF_ + i]   = w1_b[i];
        dout[m * DF_ + i]  = w2_b[i] + row[i];
    }
}

// ============================================================================
// K4/K5: GEMM v4. 4m x 4n register tile (16 acc/thread) -> 2 B smem per FMA.
// Tile 128n x 256k, grid (16 n-tiles, 8 k-splits) = 128 CTAs x 256 thr.
// cp.async 3-stage W pipeline; A transposed [k][m] staged once. RED.ADD out.
// ============================================================================
__global__ __launch_bounds__(256) void gemm_kernel(int mode,
                                                   const float* __restrict__ W,
                                                   float* __restrict__ outp) {
    __shared__ float As[256][36];                      // [k][m], 36.9 KB
    __shared__ __align__(16) float Ws[3][128][36];     // [n][k] stages, 54 KB

    const float* A = (mode == 0) ? g_LN2 : g_H;
    float* C       = (mode == 0) ? g_H   : outp;

    const int n0 = blockIdx.x * 128;
    const int k0 = blockIdx.y * 256;
    const int tid = threadIdx.x;
    const int lane = tid & 31;
    const int wid = tid >> 5;

    auto issueW = [&](int s) {
        const int buf = s % 3;
        #pragma unroll
        for (int j = 0; j < 4; ++j) {
            int idx = tid + 256 * j;           // 0..1023
            int n = idx >> 3, qd = idx & 7;
            cpasync16(&Ws[buf][n][qd * 4],
                      &W[(size_t)(n0 + n) * DF_ + k0 + s * 32 + qd * 4]);
        }
        cp_commit();
    };

    issueW(0);
    issueW(1);

    // stage A: 32m x 256k transposed
    {
        const int m = tid >> 3;
        const int kq = (tid & 7) * 4;
        #pragma unroll
        for (int it = 0; it < 8; ++it) {
            const int k = kq + 32 * it;
            float4 v = *(const float4*)&A[m * DF_ + k0 + k];
            if (mode) {
                v.x = fmaxf(v.x, 0.f); v.y = fmaxf(v.y, 0.f);
                v.z = fmaxf(v.z, 0.f); v.w = fmaxf(v.w, 0.f);
            }
            As[k + 0][m] = v.x;
            As[k + 1][m] = v.y;
            As[k + 2][m] = v.z;
            As[k + 3][m] = v.w;
        }
    }

    const int m0 = (lane & 7) * 4;
    const int nb = wid * 16 + (lane >> 3) * 4;

    float acc[16];
    #pragma unroll
    for (int i = 0; i < 16; ++i) acc[i] = 0.f;

    #pragma unroll
    for (int s = 0; s < 8; ++s) {
        if (s < 7) cp_wait<1>(); else cp_wait<0>();
        __syncthreads();
        if (s + 2 < 8) issueW(s + 2);

        const int buf = s % 3;
        #pragma unroll
        for (int k4 = 0; k4 < 8; ++k4) {
            const int kk = s * 32 + k4 * 4;
            float4 a0 = *(const float4*)&As[kk + 0][m0];
            float4 a1 = *(const float4*)&As[kk + 1][m0];
            float4 a2 = *(const float4*)&As[kk + 2][m0];
            float4 a3 = *(const float4*)&As[kk + 3][m0];
            #pragma unroll
            for (int u = 0; u < 4; ++u) {
                float4 wv = *(const float4*)&Ws[buf][nb + u][k4 * 4];
                acc[u * 4 + 0] = fmaf(a0.x, wv.x, fmaf(a1.x, wv.y, fmaf(a2.x, wv.z, fmaf(a3.x, wv.w, acc[u * 4 + 0]))));
                acc[u * 4 + 1] = fmaf(a0.y, wv.x, fmaf(a1.y, wv.y, fmaf(a2.y, wv.z, fmaf(a3.y, wv.w, acc[u * 4 + 1]))));
                acc[u * 4 + 2] = fmaf(a0.z, wv.x, fmaf(a1.z, wv.y, fmaf(a2.z, wv.z, fmaf(a3.z, wv.w, acc[u * 4 + 2]))));
                acc[u * 4 + 3] = fmaf(a0.w, wv.x, fmaf(a1.w, wv.y, fmaf(a2.w, wv.z, fmaf(a3.w, wv.w, acc[u * 4 + 3]))));
            }
        }
    }

    #pragma unroll
    for (int u = 0; u < 4; ++u)
        #pragma unroll
        for (int v = 0; v < 4; ++v)
            atomicAdd(&C[(m0 + v) * DF_ + n0 + nb + u], acc[u * 4 + v]);
}

// ============================================================================
extern "C" void kernel_launch(void* const* d_in, const int* in_sizes, int n_in,
                              void* d_out, int out_size) {
    const float* feat   = (const float*)d_in[0];
    const int*   idx    = (const int*)  d_in[1];
    const float* ln_w   = (const float*)d_in[2];
    const float* ln_b   = (const float*)d_in[3];
    const float* q_w    = (const float*)d_in[4];
    const float* k_w    = (const float*)d_in[5];
    const float* v_w    = (const float*)d_in[6];
    const float* conv_w = (const float*)d_in[7];
    const float* bn_w   = (const float*)d_in[8];
    const float* bn_b   = (const float*)d_in[9];
    const float* w1_w   = (const float*)d_in[10];
    const float* w1_b   = (const float*)d_in[11];
    const float* w2_w   = (const float*)d_in[12];
    const float* w2_b   = (const float*)d_in[13];
    float* out = (float*)d_out;

    prep_kernel<<<B_, 256>>>(feat, idx, ln_w, ln_b, q_w, k_w, v_w, conv_w);
    attn_kernel<<<dim3(B_, 16), 256>>>(feat, out);
    ffn_prep_kernel<<<B_, 256>>>(bn_w, bn_b, w1_b, w2_b, out);
    gemm_kernel<<<dim3(16, 8), 256>>>(0, w1_w, out);
    gemm_kernel<<<dim3(16, 8), 256>>>(1, w2_w, out);
}

// round 5
// speedup vs baseline: 2.3234x; 1.0613x over previous
#include <cuda_runtime.h>
#include <math.h>

#define B_   32
#define DF_  2048
#define NC_  1023
#define NCP_ 1024

typedef unsigned long long ull;

// ---- packed f32x2 helpers (Blackwell) ----
__device__ __forceinline__ ull PK(float lo, float hi) {
    ull r; asm("mov.b64 %0,{%1,%2};" : "=l"(r) : "f"(lo), "f"(hi)); return r;
}
__device__ __forceinline__ void UPK(ull v, float& a, float& b) {
    asm("mov.b64 {%0,%1},%2;" : "=f"(a), "=f"(b) : "l"(v));
}
__device__ __forceinline__ ull FMA2(ull a, ull b, ull c) {
    ull d; asm("fma.rn.f32x2 %0,%1,%2,%3;" : "=l"(d) : "l"(a), "l"(b), "l"(c)); return d;
}
__device__ __forceinline__ ull ADD2(ull a, ull b) {
    ull d; asm("add.rn.f32x2 %0,%1,%2;" : "=l"(d) : "l"(a), "l"(b)); return d;
}
__device__ __forceinline__ ull MUL2(ull a, ull b) {
    ull d; asm("mul.rn.f32x2 %0,%1,%2;" : "=l"(d) : "l"(a), "l"(b)); return d;
}

// ---- cp.async helpers ----
__device__ __forceinline__ void cpasync16(void* dst_smem, const void* src) {
    unsigned d = (unsigned)__cvta_generic_to_shared(dst_smem);
    asm volatile("cp.async.cg.shared.global [%0], [%1], 16;" :: "r"(d), "l"(src));
}
__device__ __forceinline__ void cp_commit() {
    asm volatile("cp.async.commit_group;");
}
template <int N>
__device__ __forceinline__ void cp_wait() {
    asm volatile("cp.async.wait_group %0;" :: "n"(N));
}

// ---------------- scratch ----------------
__device__ float g_LN[B_ * DF_];
__device__ float g_S[B_ * NCP_];
__device__ float g_V[B_ * NCP_];
__device__ float g_smax[B_];
__device__ float g_smin[B_];
__device__ float g_OUT1[B_ * DF_];
__device__ float g_LN2[B_ * DF_];
__device__ float g_H[B_ * DF_];

// ============================================================================
// K1: per-batch preprocess (unchanged)
// ============================================================================
__global__ void prep_kernel(const float* __restrict__ feat,
                            const int*   __restrict__ idx,
                            const float* __restrict__ ln_w,
                            const float* __restrict__ ln_b,
                            const float* __restrict__ q_w,
                            const float* __restrict__ k_w,
                            const float* __restrict__ v_w,
                            const float* __restrict__ conv_w) {
    __shared__ float sf[DF_];
    __shared__ float sh[DF_];
    __shared__ float kred[4][128];
    __shared__ float vred[4][128];
    __shared__ float red1[8], red2[8];

    const int b = blockIdx.x;
    const int tid = threadIdx.x;

    float s1 = 0.f, s2 = 0.f;
    for (int i = tid; i < DF_; i += 256) {
        float v = feat[b * DF_ + i];
        sf[i] = v;
        s1 += v;
        s2 = fmaf(v, v, s2);
    }

    if (tid < 128) {
        float qw = q_w[tid];
        float cw = conv_w[tid];
        #pragma unroll
        for (int j = 0; j < 4; j++) {
            kred[j][tid] = qw * k_w[tid * 4 + j];
            vred[j][tid] = cw * v_w[tid * 4 + j];
        }
    }

    #pragma unroll
    for (int o = 16; o; o >>= 1) {
        s1 += __shfl_xor_sync(~0u, s1, o);
        s2 += __shfl_xor_sync(~0u, s2, o);
    }
    if ((tid & 31) == 0) { red1[tid >> 5] = s1; red2[tid >> 5] = s2; }
    __syncthreads();

    if (tid < 64) {
        #pragma unroll
        for (int j = 0; j < 4; j++) {
            kred[j][tid] += kred[j][tid + 64];
            vred[j][tid] += vred[j][tid + 64];
        }
    }
    __syncthreads();
    if (tid < 32) {
        #pragma unroll
        for (int j = 0; j < 4; j++) {
            float kv = kred[j][tid] + kred[j][tid + 32];
            float vv = vred[j][tid] + vred[j][tid + 32];
            #pragma unroll
            for (int o = 16; o; o >>= 1) {
                kv += __shfl_xor_sync(~0u, kv, o);
                vv += __shfl_xor_sync(~0u, vv, o);
            }
            if (tid == 0) { kred[j][0] = kv; vred[j][0] = vv; }
        }
    }
    __syncthreads();

    float S1 = 0.f, S2 = 0.f;
    #pragma unroll
    for (int i = 0; i < 8; i++) { S1 += red1[i]; S2 += red2[i]; }
    const float mean = S1 * (1.f / DF_);
    const float var  = S2 * (1.f / DF_) - mean * mean;
    const float rstd = rsqrtf(var + 1e-5f);

    for (int i = tid; i < DF_; i += 256) {
        g_LN[b * DF_ + i] = (sf[i] - mean) * rstd * ln_w[i] + ln_b[i];
        sh[i] = sf[idx[i]];
    }
    __syncthreads();

    const float kw0 = kred[0][0], kw1 = kred[1][0], kw2 = kred[2][0], kw3 = kred[3][0];
    const float vw0 = vred[0][0], vw1 = vred[1][0], vw2 = vred[2][0], vw3 = vred[3][0];

    float lmax = -3.4e38f, lmin = 3.4e38f;
    for (int c = tid; c < NCP_; c += 256) {
        float s = 0.f, v = 0.f;
        if (c < NC_) {
            float x0 = sh[2 * c], x1 = sh[2 * c + 1], x2 = sh[2 * c + 2], x3 = sh[2 * c + 3];
            s = fmaf(x3, kw3, fmaf(x2, kw2, fmaf(x1, kw1, x0 * kw0)));
            v = fmaf(x3, vw3, fmaf(x2, vw2, fmaf(x1, vw1, x0 * vw0)));
            lmax = fmaxf(lmax, s);
            lmin = fminf(lmin, s);
        }
        g_S[b * NCP_ + c] = s;
        g_V[b * NCP_ + c] = v;
    }
    #pragma unroll
    for (int o = 16; o; o >>= 1) {
        lmax = fmaxf(lmax, __shfl_xor_sync(~0u, lmax, o));
        lmin = fminf(lmin, __shfl_xor_sync(~0u, lmin, o));
    }
    __syncthreads();
    if ((tid & 31) == 0) { red1[tid >> 5] = lmax; red2[tid >> 5] = lmin; }
    __syncthreads();
    if (tid == 0) {
        float mx = red1[0], mn = red2[0];
        #pragma unroll
        for (int i = 1; i < 8; i++) { mx = fmaxf(mx, red1[i]); mn = fminf(mn, red2[i]); }
        g_smax[b] = mx;
        g_smin[b] = mn;
    }
}

// ============================================================================
// K2: softmax + attn output. S,V pairs held in REGISTERS (loaded once per
// warp, coalesced); smem only used for the aligned-store staging buffer.
// ============================================================================
#define SBUF_PITCH 1056
__global__ __launch_bounds__(256) void attn_kernel(const float* __restrict__ feat,
                                                   float* __restrict__ dout) {
    __shared__ __align__(16) float sbuf[8 * SBUF_PITCH];

    const int b = blockIdx.x;
    const int chunk = blockIdx.y;
    const int tid = threadIdx.x;
    const int lane = tid & 31;
    const int w = tid >> 5;

    // per-thread register copies of S and V pairs (coalesced float2 loads)
    const float2* gs = (const float2*)(g_S + b * NCP_);
    const float2* gv = (const float2*)(g_V + b * NCP_);
    ull sreg[16], vreg[16];
    #pragma unroll
    for (int i = 0; i < 16; ++i) {
        float2 s2 = gs[lane + 32 * i];
        float2 v2 = gv[lane + 32 * i];
        sreg[i] = PK(s2.x, s2.y);
        vreg[i] = PK(v2.x, v2.y);
    }

    const float smax = g_smax[b];
    const float smin = g_smin[b];
    const float LOG2E = 1.4426950408889634f;
    const ull C5 = PK(0.00133335581464284f, 0.00133335581464284f);
    const ull C4 = PK(0.00961812910762848f, 0.00961812910762848f);
    const ull C3 = PK(0.05550410866482158f, 0.05550410866482158f);
    const ull C2 = PK(0.24022650695910071f, 0.24022650695910071f);
    const ull C1 = PK(0.69314718055994531f, 0.69314718055994531f);
    const ull ONE = PK(1.0f, 1.0f);

    const bool lastlane = (lane == 31);
    float* const sb = sbuf + w * SBUF_PITCH;

    for (int r = 0; r < 16; ++r) {
        const int q = chunk * 128 + r * 8 + w;
        const int row = b * DF_ + q;
        const float alpha = g_LN[row];
        const float al = alpha * LOG2E;
        const float m = (alpha >= 0.f) ? smax : smin;
        const float nb = -al * m;
        const ull al2 = PK(al, al);
        const ull nb2 = PK(nb, nb);

        ull p2[16];
        ull sum2 = PK(0.f, 0.f), dot2 = PK(0.f, 0.f);
        #pragma unroll
        for (int i = 0; i < 16; ++i) {
            ull x = FMA2(al2, sreg[i], nb2);
            ull pf = FMA2(x, C5, C4);
            pf = FMA2(x, pf, C3);
            pf = FMA2(x, pf, C2);
            pf = FMA2(x, pf, C1);
            pf = FMA2(x, pf, ONE);
            if (i == 15) {     // mask element c=1023
                float a_, b_; UPK(pf, a_, b_);
                if (lastlane) b_ = 0.f;
                pf = PK(a_, b_);
            }
            p2[i] = pf;
            sum2 = ADD2(sum2, pf);
            dot2 = FMA2(pf, vreg[i], dot2);
        }

        float slo, shi, dlo, dhi;
        UPK(sum2, slo, shi);
        UPK(dot2, dlo, dhi);
        float sum = slo + shi;
        float dot = dlo + dhi;
        #pragma unroll
        for (int o = 16; o; o >>= 1) {
            sum += __shfl_xor_sync(~0u, sum, o);
            dot += __shfl_xor_sync(~0u, dot, o);
        }
        const float inv = 1.0f / sum;
        const ull inv2 = PK(inv, inv);

        float* const base = dout + 65536 + (size_t)row * NC_;
        const int shift = (int)((size_t)base & 15) >> 2;   // = base&3 in floats
        const int lead = (4 - shift) & 3;

        // stage normalized row into sbuf at offset `shift`
        if ((shift & 1) == 0) {
            #pragma unroll
            for (int i = 0; i < 16; ++i) {
                float o0, o1; UPK(MUL2(p2[i], inv2), o0, o1);
                *(float2*)(sb + 2 * (lane + 32 * i) + shift) = make_float2(o0, o1);
            }
        } else {
            #pragma unroll
            for (int i = 0; i < 16; ++i) {
                float o0, o1; UPK(MUL2(p2[i], inv2), o0, o1);
                const int c = 2 * (lane + 32 * i) + shift;
                sb[c] = o0;
                sb[c + 1] = o1;
            }
        }
        __syncwarp();

        // coalesced, fully aligned copy-out
        if (lane < lead) __stcs(base + lane, sb[lane + shift]);
        const float4* s4 = (const float4*)(sb + lead + shift);   // 16B aligned
        float4* g4 = (float4*)(base + lead);
        #pragma unroll
        for (int j = 0; j < 8; ++j) {
            const int t = lane + 32 * j;
            if (t < 255) __stcs(g4 + t, s4[t]);
        }
        const int done = lead + 1020;
        const int tail = NC_ - done;      // 3 - lead
        if (lane < tail) __stcs(base + done + lane, sb[done + lane + shift]);

        if (lane == 0) {
            g_OUT1[row] = fmaf(dot, inv, feat[row]);
        }
        __syncwarp();
    }
}

// ============================================================================
// K3: FFN prep (unchanged)
// ============================================================================
__global__ void ffn_prep_kernel(const float* __restrict__ bn_w,
                                const float* __restrict__ bn_b,
                                const float* __restrict__ w1_b,
                                const float* __restrict__ w2_b,
                                float* __restrict__ dout) {
    __shared__ float row[DF_];
    __shared__ float red1[8], red2[8];
    const int m = blockIdx.x;
    const int tid = threadIdx.x;

    float s1 = 0.f, s2 = 0.f;
    for (int i = tid; i < DF_; i += 256) {
        float v = g_OUT1[m * DF_ + i];
        row[i] = v;
        s1 += v;
        s2 = fmaf(v, v, s2);
    }
    #pragma unroll
    for (int o = 16; o; o >>= 1) {
        s1 += __shfl_xor_sync(~0u, s1, o);
        s2 += __shfl_xor_sync(~0u, s2, o);
    }
    if ((tid & 31) == 0) { red1[tid >> 5] = s1; red2[tid >> 5] = s2; }
    __syncthreads();
    float S1 = 0.f, S2 = 0.f;
    #pragma unroll
    for (int i = 0; i < 8; i++) { S1 += red1[i]; S2 += red2[i]; }
    const float mean = S1 * (1.f / DF_);
    const float var  = S2 * (1.f / DF_) - mean * mean;
    const float rstd = rsqrtf(var + 1e-6f);

    for (int i = tid; i < DF_; i += 256) {
        g_LN2[m * DF_ + i] = (row[i] - mean) * rstd * bn_w[i] + bn_b[i];
        g_H[m * DF_ + i]   = w1_b[i];
        dout[m * DF_ + i]  = w2_b[i] + row[i];
    }
}

// ============================================================================
// K4/K5: GEMM v6. Packed f32x2 FMA inner loop: acc packed over m-pairs,
// W scalar broadcast via mov.b64 (ALU pipe, overlaps FMA pipe).
// Tile 128n x 256k, grid (16 n-tiles, 8 k-splits) = 128 CTAs x 256 thr.
// cp.async 3-stage W pipeline; A transposed [k][m] staged once. RED.ADD out.
// ============================================================================
__global__ __launch_bounds__(256) void gemm_kernel(int mode,
                                                   const float* __restrict__ W,
                                                   float* __restrict__ outp) {
    __shared__ __align__(16) float As[256][36];        // [k][m]
    __shared__ __align__(16) float Ws[3][128][36];     // [n][k] stages

    const float* A = (mode == 0) ? g_LN2 : g_H;
    float* C       = (mode == 0) ? g_H   : outp;

    const int n0 = blockIdx.x * 128;
    const int k0 = blockIdx.y * 256;
    const int tid = threadIdx.x;
    const int lane = tid & 31;
    const int wid = tid >> 5;

    auto issueW = [&](int s) {
        const int buf = s % 3;
        #pragma unroll
        for (int j = 0; j < 4; ++j) {
            int idx = tid + 256 * j;           // 0..1023
            int n = idx >> 3, qd = idx & 7;
            cpasync16(&Ws[buf][n][qd * 4],
                      &W[(size_t)(n0 + n) * DF_ + k0 + s * 32 + qd * 4]);
        }
        cp_commit();
    };

    issueW(0);
    issueW(1);

    // stage A: 32m x 256k transposed
    {
        const int m = tid >> 3;
        const int kq = (tid & 7) * 4;
        #pragma unroll
        for (int it = 0; it < 8; ++it) {
            const int k = kq + 32 * it;
            float4 v = *(const float4*)&A[m * DF_ + k0 + k];
            if (mode) {
                v.x = fmaxf(v.x, 0.f); v.y = fmaxf(v.y, 0.f);
                v.z = fmaxf(v.z, 0.f); v.w = fmaxf(v.w, 0.f);
            }
            As[k + 0][m] = v.x;
            As[k + 1][m] = v.y;
            As[k + 2][m] = v.z;
            As[k + 3][m] = v.w;
        }
    }

    const int m0 = (lane & 7) * 4;
    const int nb = wid * 16 + (lane >> 3) * 4;

    // acc2[u][p]: u = n offset (0..3), p = m pair (0: m0/m0+1, 1: m0+2/m0+3)
    ull acc2[4][2];
    #pragma unroll
    for (int u = 0; u < 4; ++u) { acc2[u][0] = PK(0.f, 0.f); acc2[u][1] = PK(0.f, 0.f); }

    #pragma unroll
    for (int s = 0; s < 8; ++s) {
        if (s < 7) cp_wait<1>(); else cp_wait<0>();
        __syncthreads();
        if (s + 2 < 8) issueW(s + 2);

        const int buf = s % 3;
        #pragma unroll
        for (int k4 = 0; k4 < 8; ++k4) {
            const int kk = s * 32 + k4 * 4;
            ull a[4][2];
            #pragma unroll
            for (int k = 0; k < 4; ++k) {
                float4 av = *(const float4*)&As[kk + k][m0];
                a[k][0] = PK(av.x, av.y);
                a[k][1] = PK(av.z, av.w);
            }
            #pragma unroll
            for (int u = 0; u < 4; ++u) {
                float4 wv = *(const float4*)&Ws[buf][nb + u][k4 * 4];
                ull w0 = PK(wv.x, wv.x);
                ull w1 = PK(wv.y, wv.y);
                ull w2 = PK(wv.z, wv.z);
                ull w3 = PK(wv.w, wv.w);
                acc2[u][0] = FMA2(a[0][0], w0, acc2[u][0]);
                acc2[u][1] = FMA2(a[0][1], w0, acc2[u][1]);
                acc2[u][0] = FMA2(a[1][0], w1, acc2[u][0]);
                acc2[u][1] = FMA2(a[1][1], w1, acc2[u][1]);
                acc2[u][0] = FMA2(a[2][0], w2, acc2[u][0]);
                acc2[u][1] = FMA2(a[2][1], w2, acc2[u][1]);
                acc2[u][0] = FMA2(a[3][0], w3, acc2[u][0]);
                acc2[u][1] = FMA2(a[3][1], w3, acc2[u][1]);
            }
        }
    }

    #pragma unroll
    for (int u = 0; u < 4; ++u) {
        float v0, v1, v2, v3;
        UPK(acc2[u][0], v0, v1);
        UPK(acc2[u][1], v2, v3);
        atomicAdd(&C[(m0 + 0) * DF_ + n0 + nb + u], v0);
        atomicAdd(&C[(m0 + 1) * DF_ + n0 + nb + u], v1);
        atomicAdd(&C[(m0 + 2) * DF_ + n0 + nb + u], v2);
        atomicAdd(&C[(m0 + 3) * DF_ + n0 + nb + u], v3);
    }
}

// ============================================================================
extern "C" void kernel_launch(void* const* d_in, const int* in_sizes, int n_in,
                              void* d_out, int out_size) {
    const float* feat   = (const float*)d_in[0];
    const int*   idx    = (const int*)  d_in[1];
    const float* ln_w   = (const float*)d_in[2];
    const float* ln_b   = (const float*)d_in[3];
    const float* q_w    = (const float*)d_in[4];
    const float* k_w    = (const float*)d_in[5];
    const float* v_w    = (const float*)d_in[6];
    const float* conv_w = (const float*)d_in[7];
    const float* bn_w   = (const float*)d_in[8];
    const float* bn_b   = (const float*)d_in[9];
    const float* w1_w   = (const float*)d_in[10];
    const float* w1_b   = (const float*)d_in[11];
    const float* w2_w   = (const float*)d_in[12];
    const float* w2_b   = (const float*)d_in[13];
    float* out = (float*)d_out;

    prep_kernel<<<B_, 256>>>(feat, idx, ln_w, ln_b, q_w, k_w, v_w, conv_w);
    attn_kernel<<<dim3(B_, 16), 256>>>(feat, out);
    ffn_prep_kernel<<<B_, 256>>>(bn_w, bn_b, w1_b, w2_b, out);
    gemm_kernel<<<dim3(16, 8), 256>>>(0, w1_w, out);
    gemm_kernel<<<dim3(16, 8), 256>>>(1, w2_w, out);
}